// round 2
// baseline (speedup 1.0000x reference)
#include <cuda_runtime.h>
#include <math_constants.h>

// Problem constants (fixed by the reference)
#define DIM   64
#define KCODE 1024
#define MAXN  262144

// Scratch (no cudaMalloc allowed)
__device__ int    g_idx[MAXN];
__device__ float  g_wsum2[KCODE];
__device__ double g_loss;

// ---------------------------------------------------------------------------
__global__ void k_zero()
{
    g_loss = 0.0;
}

// ---------------------------------------------------------------------------
// b_k = sum_d fl(w*w), sequential ascending d (mirror jnp.sum(weight**2, axis=1))
__global__ void k_wsum2(const float* __restrict__ w)
{
    int k = blockIdx.x * blockDim.x + threadIdx.x;
    if (k < KCODE) {
        const float* r = w + (size_t)k * DIM;
        float s = 0.0f;
        #pragma unroll
        for (int d = 0; d < DIM; ++d)
            s = __fadd_rn(s, __fmul_rn(r[d], r[d]));
        g_wsum2[k] = s;
    }
}

// ---------------------------------------------------------------------------
// Argmin over 1024 codes.
// distance = fl( fl(a_i + b_k) - fl(2 * dot(z_i, w_k)) )
// dot accumulated sequentially over d (single accumulator per code).
// Tie-break: strict less-than -> first (lowest) index wins, matching argmin.
__global__ __launch_bounds__(256, 2)
void k_argmin(const float* __restrict__ z,
              const float* __restrict__ w,
              float* __restrict__ out_idx)
{
    __shared__ float sW[32 * DIM];   // 8 KB code tile
    __shared__ float sB[32];

    const int tid = threadIdx.x;
    const size_t token = (size_t)blockIdx.x * 256 + tid;

    // z row -> registers (fully unrolled so it stays in regs)
    float zr[DIM];
    {
        const float4* zsrc = (const float4*)(z + token * DIM);
        #pragma unroll
        for (int i = 0; i < DIM / 4; ++i) {
            float4 v = zsrc[i];
            zr[4 * i + 0] = v.x; zr[4 * i + 1] = v.y;
            zr[4 * i + 2] = v.z; zr[4 * i + 3] = v.w;
        }
    }

    // a_i = sum_d fl(z*z), sequential (mirror jnp.sum(z**2, axis=1))
    float a = 0.0f;
    #pragma unroll
    for (int d = 0; d < DIM; ++d)
        a = __fadd_rn(a, __fmul_rn(zr[d], zr[d]));

    float best = CUDART_INF_F;
    int   bidx = 0;

    for (int kt = 0; kt < KCODE / 32; ++kt) {
        __syncthreads();
        // stage 32x64 weight tile (2048 floats) with 256 threads x 2 float4
        {
            const float4* wsrc = (const float4*)(w + (size_t)kt * 32 * DIM);
            float4* wdst = (float4*)sW;
            wdst[tid]       = wsrc[tid];
            wdst[tid + 256] = wsrc[tid + 256];
            if (tid < 32) sB[tid] = g_wsum2[kt * 32 + tid];
        }
        __syncthreads();

        #pragma unroll 1
        for (int k = 0; k < 32; k += 4) {
            const float4* w0 = (const float4*)(sW + (k + 0) * DIM);
            const float4* w1 = (const float4*)(sW + (k + 1) * DIM);
            const float4* w2 = (const float4*)(sW + (k + 2) * DIM);
            const float4* w3 = (const float4*)(sW + (k + 3) * DIM);
            float acc0 = 0.0f, acc1 = 0.0f, acc2 = 0.0f, acc3 = 0.0f;
            #pragma unroll
            for (int q = 0; q < DIM / 4; ++q) {
                const float4 v0 = w0[q], v1 = w1[q], v2 = w2[q], v3 = w3[q];
                const float z0 = zr[4 * q + 0], z1 = zr[4 * q + 1];
                const float z2 = zr[4 * q + 2], z3 = zr[4 * q + 3];
                acc0 = __fmaf_rn(z0, v0.x, acc0);
                acc1 = __fmaf_rn(z0, v1.x, acc1);
                acc2 = __fmaf_rn(z0, v2.x, acc2);
                acc3 = __fmaf_rn(z0, v3.x, acc3);
                acc0 = __fmaf_rn(z1, v0.y, acc0);
                acc1 = __fmaf_rn(z1, v1.y, acc1);
                acc2 = __fmaf_rn(z1, v2.y, acc2);
                acc3 = __fmaf_rn(z1, v3.y, acc3);
                acc0 = __fmaf_rn(z2, v0.z, acc0);
                acc1 = __fmaf_rn(z2, v1.z, acc1);
                acc2 = __fmaf_rn(z2, v2.z, acc2);
                acc3 = __fmaf_rn(z2, v3.z, acc3);
                acc0 = __fmaf_rn(z3, v0.w, acc0);
                acc1 = __fmaf_rn(z3, v1.w, acc1);
                acc2 = __fmaf_rn(z3, v2.w, acc2);
                acc3 = __fmaf_rn(z3, v3.w, acc3);
            }
            const int kb = kt * 32 + k;
            float t, dd;
            t  = __fadd_rn(a, sB[k + 0]);
            dd = __fadd_rn(t, -__fmul_rn(2.0f, acc0));
            if (dd < best) { best = dd; bidx = kb + 0; }
            t  = __fadd_rn(a, sB[k + 1]);
            dd = __fadd_rn(t, -__fmul_rn(2.0f, acc1));
            if (dd < best) { best = dd; bidx = kb + 1; }
            t  = __fadd_rn(a, sB[k + 2]);
            dd = __fadd_rn(t, -__fmul_rn(2.0f, acc2));
            if (dd < best) { best = dd; bidx = kb + 2; }
            t  = __fadd_rn(a, sB[k + 3]);
            dd = __fadd_rn(t, -__fmul_rn(2.0f, acc3));
            if (dd < best) { best = dd; bidx = kb + 3; }
        }
    }

    g_idx[token]   = bidx;
    out_idx[token] = (float)bidx;
}

// ---------------------------------------------------------------------------
// Gather z_q_st = fl(z + fl(w[idx] - z)) and accumulate loss sum in double.
// 16 tokens per block, 16 threads (float4 lanes) per token.
__global__ void k_gather(const float* __restrict__ z,
                         const float* __restrict__ w,
                         float* __restrict__ out_zq)
{
    __shared__ double sred[256];
    const int tid = threadIdx.x;
    const size_t token = (size_t)blockIdx.x * 16 + (tid >> 4);
    const int c = tid & 15;

    const int idx = g_idx[token];
    const float4 wv = ((const float4*)(w + (size_t)idx * DIM))[c];
    const float4 zv = ((const float4*)(z + token * DIM))[c];

    const float dx = __fsub_rn(wv.x, zv.x);
    const float dy = __fsub_rn(wv.y, zv.y);
    const float dz = __fsub_rn(wv.z, zv.z);
    const float dw = __fsub_rn(wv.w, zv.w);

    float4 o;
    o.x = __fadd_rn(zv.x, dx);
    o.y = __fadd_rn(zv.y, dy);
    o.z = __fadd_rn(zv.z, dz);
    o.w = __fadd_rn(zv.w, dw);
    ((float4*)out_zq)[token * (DIM / 4) + c] = o;

    double s = (double)__fmul_rn(dx, dx);
    s += (double)__fmul_rn(dy, dy);
    s += (double)__fmul_rn(dz, dz);
    s += (double)__fmul_rn(dw, dw);
    sred[tid] = s;
    __syncthreads();

    #pragma unroll
    for (int off = 128; off > 0; off >>= 1) {
        if (tid < off) sred[tid] += sred[tid + off];
        __syncthreads();
    }
    if (tid == 0) atomicAdd(&g_loss, sred[0]);
}

// ---------------------------------------------------------------------------
__global__ void k_final(float* __restrict__ out_loss, int total_elems)
{
    const float m = (float)(g_loss / (double)total_elems);
    // loss = q_latent + 0.25 * e_latent, both equal m numerically
    out_loss[0] = __fadd_rn(m, __fmul_rn(0.25f, m));
}

// ---------------------------------------------------------------------------
extern "C" void kernel_launch(void* const* d_in, const int* in_sizes, int n_in,
                              void* d_out, int out_size)
{
    const float* z = (const float*)d_in[0];   // (N, 64) fp32
    const float* w = (const float*)d_in[1];   // (1024, 64) fp32

    const int ND = in_sizes[0];
    const int N  = ND / DIM;                  // 262144

    float* out       = (float*)d_out;
    float* out_zq    = out;                    // N*64 floats
    float* out_loss  = out + (size_t)N * DIM;  // 1 float
    float* out_idx   = out_loss + 1;           // N floats

    k_zero<<<1, 1>>>();
    k_wsum2<<<(KCODE + 255) / 256, 256>>>(w);
    k_argmin<<<N / 256, 256>>>(z, w, out_idx);
    k_gather<<<N / 16, 256>>>(z, w, out_zq);
    k_final<<<1, 1>>>(out_loss, ND);
}